// round 13
// baseline (speedup 1.0000x reference)
#include <cuda_runtime.h>
#include <cuda_fp16.h>
#include <math.h>
#include <stdint.h>

#define BATCH 4
#define SEQ   2048
#define HID   256
#define NTOK  (BATCH*SEQ)   // 8192
#define NHEAD 8
#define DPH   32
#define WINSZ 64
#define NWIN  32

#define WSCALE     256.0f
#define WSCALE_INV 0.00390625f

// ---------------- scratch (no allocs allowed) ----------------
__device__ __half g_qf[NTOK*HID];     // q (scaled) fp16
__device__ __half g_kf[NTOK*HID];     // k fp16
__device__ __half g_vf[NTOK*HID];     // v fp16
__device__ __half g_pef[NTOK*HID];    // pe fp16

__device__ __half g_af[NTOK*HID];     // inputs fp16
__device__ __half g_pe1[NTOK*HID];    // pos-mlp stage1 fp16
__device__ __half g_ctxf[NTOK*HID];   // attn output fp16
__device__ __half g_wh[5*HID*HID];    // weights*256, TRANSPOSED [n][k], fp16 hi
__device__ __half g_wl[5*HID*HID];    // residual lo

__device__ __forceinline__ float gelu_exact(float x) {
    return 0.5f * x * (1.0f + erff(x * 0.70710678118654752f));
}
__device__ __forceinline__ uint32_t pkhf(float a, float b) {
    __half2 h = __floats2half2_rn(a, b);
    return *reinterpret_cast<uint32_t*>(&h);
}

__device__ __forceinline__ void ldsm4(uint32_t* r, const void* p) {
    uint32_t a = (uint32_t)__cvta_generic_to_shared(p);
    asm volatile("ldmatrix.sync.aligned.m8n8.x4.shared.b16 {%0,%1,%2,%3}, [%4];"
                 : "=r"(r[0]), "=r"(r[1]), "=r"(r[2]), "=r"(r[3]) : "r"(a));
}
__device__ __forceinline__ void ldsm4t(uint32_t* r, const void* p) {
    uint32_t a = (uint32_t)__cvta_generic_to_shared(p);
    asm volatile("ldmatrix.sync.aligned.m8n8.x4.trans.shared.b16 {%0,%1,%2,%3}, [%4];"
                 : "=r"(r[0]), "=r"(r[1]), "=r"(r[2]), "=r"(r[3]) : "r"(a));
}
__device__ __forceinline__ void mma_f16(float* d, const uint32_t* a,
                                        uint32_t b0, uint32_t b1) {
    asm volatile(
        "mma.sync.aligned.m16n8k16.row.col.f32.f16.f16.f32 "
        "{%0,%1,%2,%3}, {%4,%5,%6,%7}, {%8,%9}, {%0,%1,%2,%3};\n"
        : "+f"(d[0]), "+f"(d[1]), "+f"(d[2]), "+f"(d[3])
        : "r"(a[0]), "r"(a[1]), "r"(a[2]), "r"(a[3]), "r"(b0), "r"(b1));
}
__device__ __forceinline__ void cpa16(uint32_t s, const void* g) {
    asm volatile("cp.async.cg.shared.global [%0], [%1], 16;" :: "r"(s), "l"(g));
}
__device__ __forceinline__ void cpa_commit() { asm volatile("cp.async.commit_group;"); }
__device__ __forceinline__ void cpa_wait1()  { asm volatile("cp.async.wait_group 1;"); }
__device__ __forceinline__ void cpa_wait0()  { asm volatile("cp.async.wait_group 0;"); }

// ================= fused prep: weights + inputs + pos1 (incl. stats) =================
// blocks [0,80): weight transpose+split; [80,2128): input cvt; [2128,2384): pos1
__global__ __launch_bounds__(256) void prep_all(
    const float* __restrict__ wq, const float* __restrict__ wk,
    const float* __restrict__ wv, const float* __restrict__ p2w,
    const float* __restrict__ wo, const float* __restrict__ A,
    const float* __restrict__ p1w, const float* __restrict__ p1b,
    const float* __restrict__ lng, const float* __restrict__ lnb,
    const float* __restrict__ p)
{
    __shared__ float t[64][65];
    __shared__ float red[8];
    const int bid = blockIdx.x;
    const int tid = threadIdx.x;

    if (bid < 80) {
        const int w = bid >> 4;
        const float* src = (w == 0) ? wq : (w == 1) ? wk : (w == 2) ? wv :
                           (w == 3) ? p2w : wo;
        const int y = bid & 15;
        const int n0 = (y & 3) * 64, k0 = (y >> 2) * 64;
#pragma unroll
        for (int i = 0; i < 4; i++) {
            int f = i * 256 + tid;
            int kr = f >> 4, nc = (f & 15) * 4;
            float4 v = *(const float4*)(src + (size_t)(k0 + kr) * 256 + n0 + nc);
            t[kr][nc] = v.x; t[kr][nc+1] = v.y; t[kr][nc+2] = v.z; t[kr][nc+3] = v.w;
        }
        __syncthreads();
#pragma unroll
        for (int i = 0; i < 4; i++) {
            int f = i * 256 + tid;
            int nr = f >> 4, kc = (f & 15) * 4;
            size_t o = (size_t)w * 65536 + (size_t)(n0 + nr) * 256 + k0 + kc;
#pragma unroll
            for (int j = 0; j < 4; j++) {
                float v = t[kc + j][nr] * WSCALE;
                __half h = __float2half_rn(v);
                g_wh[o + j] = h;
                g_wl[o + j] = __float2half_rn(v - __half2float(h));
            }
        }
    } else if (bid < 2128) {
        const int idx = ((bid - 80) * 256 + tid) * 4;
        float4 v = *(const float4*)(A + idx);
        uint2 o;
        o.x = pkhf(v.x, v.y);
        o.y = pkhf(v.z, v.w);
        *(uint2*)(&g_af[idx]) = o;
    } else {
        // ---- pos1: self-contained stats + 32 tokens (tid = channel) ----
        const int lane = tid & 31, warp = tid >> 5;
        const float w0 = p1w[tid], w1 = p1w[256 + tid], b0 = p1b[tid];
        const float gg = lng[tid], bb = lnb[tid];

        float vals[6];
        float outm[3];
        vals[0] = w0; vals[1] = w1; vals[2] = b0;
#pragma unroll
        for (int s = 0; s < 3; s++) {
            float v = vals[s];
#pragma unroll
            for (int o = 16; o; o >>= 1) v += __shfl_xor_sync(0xffffffffu, v, o);
            if (lane == 0) red[warp] = v;
            __syncthreads();
            float tot = 0.f;
#pragma unroll
            for (int i = 0; i < 8; i++) tot += red[i];
            outm[s] = tot * (1.f / 256.f);
            __syncthreads();
        }
        const float a = w0 - outm[0], bcn = w1 - outm[1], c = b0 - outm[2];
        const float Ac = a * gg, Bc = bcn * gg, Cc = c * gg;
        vals[0] = a*a; vals[1] = bcn*bcn; vals[2] = a*bcn;
        vals[3] = a*c; vals[4] = bcn*c; vals[5] = c*c;
        float S[6];
#pragma unroll
        for (int s = 0; s < 6; s++) {
            float v = vals[s];
#pragma unroll
            for (int o = 16; o; o >>= 1) v += __shfl_xor_sync(0xffffffffu, v, o);
            if (lane == 0) red[warp] = v;
            __syncthreads();
            float tot = 0.f;
#pragma unroll
            for (int i = 0; i < 8; i++) tot += red[i];
            S[s] = tot * (1.f / 256.f);
            __syncthreads();
        }

        const int tokbase = (bid - 2128) * 32;
#pragma unroll 4
        for (int tt = 0; tt < 32; tt++) {
            const int tok = tokbase + tt;
            const float2 pp = *(const float2*)(p + tok * 2);
            const float var = pp.x*pp.x*S[0] + pp.y*pp.y*S[1] + 2.f*pp.x*pp.y*S[2]
                            + 2.f*pp.x*S[3] + 2.f*pp.y*S[4] + S[5];
            const float rstd = rsqrtf(var + 1e-6f);
            const float yv = gelu_exact((pp.x * Ac + pp.y * Bc + Cc) * rstd + bb);
            g_pe1[(size_t)tok * 256 + tid] = __float2half_rn(yv);
        }
    }
}

// ================= fp16 2-term GEMM, BM=64/BN=128 (2 blocks/SM) =================
#define OA  0
#define OWH 5120
#define OWL 15360
#define STG 25600
#define GSMEM (2*STG)   // 51200

extern __shared__ char dsm[];

__device__ __forceinline__ void tile_loads(
    const __half* Af, const __half* Wh, const __half* Wl,
    int m0, int n0, int kt, int st, uint32_t smem_u32, int tid)
{
    const uint32_t sb = smem_u32 + st * STG;
    {
        int row = tid >> 2, ch = tid & 3;
        cpa16(sb + OA + row * 80 + ch * 16,
              Af + (size_t)(m0 + row) * 256 + kt * 32 + ch * 8);
    }
#pragma unroll
    for (int i = 0; i < 2; i++) {
        int f = i * 256 + tid;
        int row = f >> 2, ch = f & 3;
        const uint32_t so = row * 80 + ch * 16;
        const size_t gkb = (size_t)(n0 + row) * 256 + kt * 32 + ch * 8;
        cpa16(sb + OWH + so, Wh + gkb);
        cpa16(sb + OWL + so, Wl + gkb);
    }
}

// If Ch != nullptr -> write fp16 to Ch, else fp32 to Cf.
__device__ __forceinline__ void gemm_core(
    const __half* __restrict__ Af,
    const __half* __restrict__ Wh, const __half* __restrict__ Wl,
    const float* __restrict__ bias, float* __restrict__ Cf,
    __half* __restrict__ Ch,
    float scale, int act, int bx, int by)
{
    const int tid  = threadIdx.x;
    const int wid  = tid >> 5;
    const int lane = tid & 31;
    const int g = lane >> 2;
    const int q = lane & 3;
    const int wm = (wid & 1) * 32;     // 2 m-warps over BM=64
    const int wn = (wid >> 1) * 32;    // 4 n-warps over BN=128
    const int m0 = bx * 64;
    const int n0 = by * 128;
    const uint32_t smem_u32 = (uint32_t)__cvta_generic_to_shared(dsm);

    float acc[2][4][4];
#pragma unroll
    for (int mt = 0; mt < 2; mt++)
#pragma unroll
        for (int nt = 0; nt < 4; nt++)
#pragma unroll
            for (int i = 0; i < 4; i++) acc[mt][nt][i] = 0.f;

    tile_loads(Af, Wh, Wl, m0, n0, 0, 0, smem_u32, tid);
    cpa_commit();

    const int la = lane & 15;
    const int khalf = (lane >> 4) * 16;

    for (int it = 0; it < 8; it++) {
        if (it < 7) {
            tile_loads(Af, Wh, Wl, m0, n0, it + 1, (it + 1) & 1, smem_u32, tid);
            cpa_commit();
            cpa_wait1();
        } else {
            cpa_wait0();
        }
        __syncthreads();

        const char* sb = dsm + (it & 1) * STG;
#pragma unroll
        for (int ks = 0; ks < 2; ks++) {
            const int kb = ks * 32 + khalf;
            uint32_t a[2][4], bh[2][4], bl[2][4];
#pragma unroll
            for (int mt = 0; mt < 2; mt++)
                ldsm4(a[mt], sb + OA + (wm + mt * 16 + la) * 80 + kb);
#pragma unroll
            for (int np = 0; np < 2; np++) {
                ldsm4(bh[np], sb + OWH + (wn + np * 16 + la) * 80 + kb);
                ldsm4(bl[np], sb + OWL + (wn + np * 16 + la) * 80 + kb);
            }
#pragma unroll
            for (int mt = 0; mt < 2; mt++)
#pragma unroll
                for (int nt = 0; nt < 4; nt++) {
                    const int np = nt >> 1, j = nt & 1;
                    mma_f16(acc[mt][nt], a[mt], bh[np][j], bh[np][j + 2]);
                    mma_f16(acc[mt][nt], a[mt], bl[np][j], bl[np][j + 2]);
                }
        }
        __syncthreads();
    }

#pragma unroll
    for (int mt = 0; mt < 2; mt++) {
        int r0 = m0 + wm + mt * 16 + g;
#pragma unroll
        for (int nt = 0; nt < 4; nt++) {
            int cn = n0 + wn + nt * 8 + 2 * q;
            float2 b2 = *(const float2*)(bias + cn);
            float v0 = (acc[mt][nt][0] * WSCALE_INV + b2.x) * scale;
            float v1 = (acc[mt][nt][1] * WSCALE_INV + b2.y) * scale;
            float v2 = (acc[mt][nt][2] * WSCALE_INV + b2.x) * scale;
            float v3 = (acc[mt][nt][3] * WSCALE_INV + b2.y) * scale;
            if (act) {
                v0 = gelu_exact(v0); v1 = gelu_exact(v1);
                v2 = gelu_exact(v2); v3 = gelu_exact(v3);
            }
            if (Ch) {
                *(uint32_t*)(Ch + (size_t)r0 * 256 + cn)       = pkhf(v0, v1);
                *(uint32_t*)(Ch + (size_t)(r0 + 8) * 256 + cn) = pkhf(v2, v3);
            } else {
                *(float2*)(Cf + (size_t)r0 * 256 + cn)       = make_float2(v0, v1);
                *(float2*)(Cf + (size_t)(r0 + 8) * 256 + cn) = make_float2(v2, v3);
            }
        }
    }
}

// fused Q/K/V/PE: blockIdx.z selects; all write fp16
__global__ __launch_bounds__(256, 2) void gemm4(
    const float* __restrict__ bq, const float* __restrict__ bk,
    const float* __restrict__ bv, const float* __restrict__ p2b)
{
    const int z = blockIdx.z;
    const __half* Af = (z == 3) ? g_pe1 : g_af;
    const float* bias = (z == 0) ? bq : (z == 1) ? bk : (z == 2) ? bv : p2b;
    __half* Ch = (z == 0) ? g_qf : (z == 1) ? g_kf : (z == 2) ? g_vf : g_pef;
    float scale = (z == 0) ? 0.17677669529663689f : 1.f;
    gemm_core(Af, g_wh + (size_t)z * 65536, g_wl + (size_t)z * 65536,
              bias, nullptr, Ch, scale, (z == 3) ? 1 : 0, blockIdx.x, blockIdx.y);
}
__global__ __launch_bounds__(256, 2) void gemm_out(const float* __restrict__ bo,
                                                   float* __restrict__ out)
{
    gemm_core(g_ctxf, g_wh + (size_t)4 * 65536, g_wl + (size_t)4 * 65536,
              bo, out, nullptr, 1.f, 0, blockIdx.x, blockIdx.y);
}

// ================= windowed attention (fp16 inputs, batched loads) =================
// S[i,j] = q_i·(k_j - pe_j) + (c·k_j - d·pe_j) + (q_i + d)·pe_i
__global__ __launch_bounds__(128) void attn_k(
    const float* __restrict__ cvec, const float* __restrict__ dvec)
{
    const int w = blockIdx.x, h = blockIdx.y, b = blockIdx.z;

    __shared__ __half sq[64][40];
    __shared__ __half skw[64][40];
    __shared__ __half sv[64][40];
    __shared__ float sbias[64];
    __shared__ float su[64];

    const int t = threadIdx.x;
    const int tok = t >> 1;
    const int l = t & 1;
    const int dl = l * 16;

    const int s = w * 64 + tok;
    const int o = s >> 4, r = s & 15;
    const int ic = ((o & 63) << 1) + (o >> 6);
    const int orig = ic * 16 + r;
    const size_t base = ((size_t)(b * SEQ + orig)) * 256 + h * 32 + dl;

    const float* cp = cvec + h * 32 + dl;
    const float* dp = dvec + h * 32 + dl;

    // ---- issue ALL global loads before any dependent processing ----
    uint4 xq[2], xk[2], xv[2], xp[2];
#pragma unroll
    for (int ii = 0; ii < 2; ii++) {
        const int i = ii * 8;
        xq[ii] = *(const uint4*)(g_qf + base + i);
        xk[ii] = *(const uint4*)(g_kf + base + i);
        xv[ii] = *(const uint4*)(g_vf + base + i);
        xp[ii] = *(const uint4*)(g_pef + base + i);
    }

    float bias_p = 0.f, u_p = 0.f;
#pragma unroll
    for (int ii = 0; ii < 2; ii++) {
        const int i = ii * 8;
        float4 xc0 = *(const float4*)(cp + i);
        float4 xc1 = *(const float4*)(cp + i + 4);
        float4 xd0 = *(const float4*)(dp + i);
        float4 xd1 = *(const float4*)(dp + i + 4);

        *(uint4*)(&sq[tok][dl + i]) = xq[ii];
        *(uint4*)(&sv[tok][dl + i]) = xv[ii];

        uint4 kw;
        const __half2* k2 = (const __half2*)&xk[ii];
        const __half2* p2 = (const __half2*)&xp[ii];
        const __half2* q2 = (const __half2*)&xq[ii];
        __half2* w2 = (__half2*)&kw;
#pragma unroll
        for (int j = 0; j < 4; j++) w2[j] = __hsub2(k2[j], p2[j]);
        *(uint4*)(&skw[tok][dl + i]) = kw;

        float cv4[8] = {xc0.x, xc0.y, xc0.z, xc0.w, xc1.x, xc1.y, xc1.z, xc1.w};
        float dv4[8] = {xd0.x, xd0.y, xd0.z, xd0.w, xd1.x, xd1.y, xd1.z, xd1.w};
#pragma unroll
        for (int j = 0; j < 4; j++) {
            float2 fk = __half22float2(k2[j]);
            float2 fp = __half22float2(p2[j]);
            float2 fq = __half22float2(q2[j]);
            bias_p += cv4[2*j] * fk.x + cv4[2*j+1] * fk.y;
            bias_p -= dv4[2*j] * fp.x + dv4[2*j+1] * fp.y;
            u_p += (fq.x + dv4[2*j]) * fp.x + (fq.y + dv4[2*j+1]) * fp.y;
        }
    }
    bias_p += __shfl_xor_sync(0xffffffffu, bias_p, 1);
    u_p    += __shfl_xor_sync(0xffffffffu, u_p, 1);
    if (l == 0) { sbias[tok] = bias_p; su[tok] = u_p; }
    __syncthreads();

    const int warp = t >> 5, lane = t & 31;
    const int la = lane & 15, lo8 = (lane >> 4) << 3;
    const int g = lane >> 2, q = lane & 3;
    const int r0 = warp * 16;

    float sacc[8][4];
#pragma unroll
    for (int j = 0; j < 8; j++)
#pragma unroll
        for (int i = 0; i < 4; i++) sacc[j][i] = 0.f;

#pragma unroll
    for (int ks = 0; ks < 2; ks++) {
        uint32_t a[4];
        ldsm4(a, &sq[r0 + la][ks * 16 + lo8]);
#pragma unroll
        for (int np = 0; np < 4; np++) {
            uint32_t bk[4];
            ldsm4(bk, &skw[np * 16 + la][ks * 16 + lo8]);
            mma_f16(sacc[2 * np],     a, bk[0], bk[2]);
            mma_f16(sacc[2 * np + 1], a, bk[1], bk[3]);
        }
    }

    const int rg = r0 + g;
    const float ug  = su[rg];
    const float ug8 = su[rg + 8];
    float m1 = -1e30f, m2 = -1e30f;
#pragma unroll
    for (int j = 0; j < 8; j++) {
        const int c0 = 8 * j + 2 * q;
        const float b0 = sbias[c0], b1 = sbias[c0 + 1];
        sacc[j][0] += ug  + b0; sacc[j][1] += ug  + b1;
        sacc[j][2] += ug8 + b0; sacc[j][3] += ug8 + b1;
        m1 = fmaxf(m1, fmaxf(sacc[j][0], sacc[j][1]));
        m2 = fmaxf(m2, fmaxf(sacc[j][2], sacc[j][3]));
    }
    m1 = fmaxf(m1, __shfl_xor_sync(0xffffffffu, m1, 1));
    m1 = fmaxf(m1, __shfl_xor_sync(0xffffffffu, m1, 2));
    m2 = fmaxf(m2, __shfl_xor_sync(0xffffffffu, m2, 1));
    m2 = fmaxf(m2, __shfl_xor_sync(0xffffffffu, m2, 2));

    float s1 = 0.f, s2 = 0.f;
    uint32_t pf[8], ph[8];
#pragma unroll
    for (int j = 0; j < 8; j++) {
        float e0 = __expf(sacc[j][0] - m1);
        float e1 = __expf(sacc[j][1] - m1);
        float e2 = __expf(sacc[j][2] - m2);
        float e3 = __expf(sacc[j][3] - m2);
        s1 += e0 + e1; s2 += e2 + e3;
        pf[j] = pkhf(e0, e1);
        ph[j] = pkhf(e2, e3);
    }
    s1 += __shfl_xor_sync(0xffffffffu, s1, 1);
    s1 += __shfl_xor_sync(0xffffffffu, s1, 2);
    s2 += __shfl_xor_sync(0xffffffffu, s2, 1);
    s2 += __shfl_xor_sync(0xffffffffu, s2, 2);
    const float inv1 = 1.f / s1;
    const float inv2 = 1.f / s2;

    float oacc[4][4];
#pragma unroll
    for (int j = 0; j < 4; j++)
#pragma unroll
        for (int i = 0; i < 4; i++) oacc[j][i] = 0.f;

#pragma unroll
    for (int kk = 0; kk < 4; kk++) {
        uint32_t a[4] = {pf[2 * kk], ph[2 * kk], pf[2 * kk + 1], ph[2 * kk + 1]};
#pragma unroll
        for (int np = 0; np < 2; np++) {
            uint32_t bv[4];
            ldsm4t(bv, &sv[kk * 16 + la][np * 16 + lo8]);
            mma_f16(oacc[2 * np],     a, bv[0], bv[1]);
            mma_f16(oacc[2 * np + 1], a, bv[2], bv[3]);
        }
    }

    {
        const int s_a = w * 64 + rg;
        const int oa_ = s_a >> 4, ra_ = s_a & 15;
        const int orig_a = (((oa_ & 63) << 1) + (oa_ >> 6)) * 16 + ra_;
        const size_t ba = ((size_t)(b * SEQ + orig_a)) * 256 + h * 32;
        const int s_b2 = w * 64 + rg + 8;
        const int ob_ = s_b2 >> 4, rb_ = s_b2 & 15;
        const int orig_b = (((ob_ & 63) << 1) + (ob_ >> 6)) * 16 + rb_;
        const size_t bb = ((size_t)(b * SEQ + orig_b)) * 256 + h * 32;
#pragma unroll
        for (int nt = 0; nt < 4; nt++) {
            const int d0 = 8 * nt + 2 * q;
            *(uint32_t*)(&g_ctxf[ba + d0]) = pkhf(oacc[nt][0] * inv1, oacc[nt][1] * inv1);
            *(uint32_t*)(&g_ctxf[bb + d0]) = pkhf(oacc[nt][2] * inv2, oacc[nt][3] * inv2);
        }
    }
}

// ================= launch =================
extern "C" void kernel_launch(void* const* d_in, const int* in_sizes, int n_in,
                              void* d_out, int out_size)
{
    const float* inputs = (const float*)d_in[0];
    const float* p      = (const float*)d_in[1];
    const float* wq     = (const float*)d_in[2];
    const float* bq     = (const float*)d_in[3];
    const float* wk     = (const float*)d_in[4];
    const float* bk     = (const float*)d_in[5];
    const float* wv     = (const float*)d_in[6];
    const float* bv     = (const float*)d_in[7];
    const float* wo     = (const float*)d_in[8];
    const float* bo     = (const float*)d_in[9];
    const float* p1w    = (const float*)d_in[10];
    const float* p1b    = (const float*)d_in[11];
    const float* p2w    = (const float*)d_in[12];
    const float* p2b    = (const float*)d_in[13];
    const float* lng    = (const float*)d_in[14];
    const float* lnb    = (const float*)d_in[15];
    const float* cv     = (const float*)d_in[16];
    const float* dv     = (const float*)d_in[17];
    float* out = (float*)d_out;

    cudaFuncSetAttribute(gemm4,    cudaFuncAttributeMaxDynamicSharedMemorySize, GSMEM);
    cudaFuncSetAttribute(gemm_out, cudaFuncAttributeMaxDynamicSharedMemorySize, GSMEM);

    prep_all<<<2384, 256>>>(wq, wk, wv, p2w, wo, inputs, p1w, p1b, lng, lnb, p);
    gemm4<<<dim3(128, 2, 4), 256, GSMEM>>>(bq, bk, bv, p2b);
    attn_k<<<dim3(NWIN, NHEAD, BATCH), 128>>>(cv, dv);
    gemm_out<<<dim3(128, 2), 256, GSMEM>>>(bo, out);
}

// round 14
// speedup vs baseline: 1.1535x; 1.1535x over previous
#include <cuda_runtime.h>
#include <cuda_fp16.h>
#include <math.h>
#include <stdint.h>

#define BATCH 4
#define SEQ   2048
#define HID   256
#define NTOK  (BATCH*SEQ)   // 8192
#define NHEAD 8
#define DPH   32
#define WINSZ 64
#define NWIN  32

#define WSCALE     256.0f
#define WSCALE_INV 0.00390625f

// ---------------- scratch (no allocs allowed) ----------------
__device__ __half g_qf[NTOK*HID];     // q (scaled) fp16
__device__ __half g_kf[NTOK*HID];     // k fp16
__device__ __half g_vf[NTOK*HID];     // v fp16
__device__ __half g_pef[NTOK*HID];    // pe fp16

__device__ __half g_af[NTOK*HID];     // inputs fp16
__device__ __half g_pe1[NTOK*HID];    // pos-mlp stage1 fp16
__device__ __half g_ctxf[NTOK*HID];   // attn output fp16
__device__ __half g_wh[5*HID*HID];    // weights*256, TRANSPOSED [n][k], fp16 hi
__device__ __half g_wl[5*HID*HID];    // residual lo

__device__ float g_A2[HID], g_B2[HID], g_C2[HID];  // centered pos1 weights * ln_g
__device__ float g_pstat[6];                       // Saa,Sbb,Sab,Sac,Sbc,Scc

__device__ __forceinline__ float gelu_exact(float x) {
    return 0.5f * x * (1.0f + erff(x * 0.70710678118654752f));
}
__device__ __forceinline__ uint32_t pkhf(float a, float b) {
    __half2 h = __floats2half2_rn(a, b);
    return *reinterpret_cast<uint32_t*>(&h);
}

__device__ __forceinline__ void ldsm4(uint32_t* r, const void* p) {
    uint32_t a = (uint32_t)__cvta_generic_to_shared(p);
    asm volatile("ldmatrix.sync.aligned.m8n8.x4.shared.b16 {%0,%1,%2,%3}, [%4];"
                 : "=r"(r[0]), "=r"(r[1]), "=r"(r[2]), "=r"(r[3]) : "r"(a));
}
__device__ __forceinline__ void ldsm4t(uint32_t* r, const void* p) {
    uint32_t a = (uint32_t)__cvta_generic_to_shared(p);
    asm volatile("ldmatrix.sync.aligned.m8n8.x4.trans.shared.b16 {%0,%1,%2,%3}, [%4];"
                 : "=r"(r[0]), "=r"(r[1]), "=r"(r[2]), "=r"(r[3]) : "r"(a));
}
__device__ __forceinline__ void mma_f16(float* d, const uint32_t* a,
                                        uint32_t b0, uint32_t b1) {
    asm volatile(
        "mma.sync.aligned.m16n8k16.row.col.f32.f16.f16.f32 "
        "{%0,%1,%2,%3}, {%4,%5,%6,%7}, {%8,%9}, {%0,%1,%2,%3};\n"
        : "+f"(d[0]), "+f"(d[1]), "+f"(d[2]), "+f"(d[3])
        : "r"(a[0]), "r"(a[1]), "r"(a[2]), "r"(a[3]), "r"(b0), "r"(b1));
}
__device__ __forceinline__ void cpa16(uint32_t s, const void* g) {
    asm volatile("cp.async.cg.shared.global [%0], [%1], 16;" :: "r"(s), "l"(g));
}
__device__ __forceinline__ void cpa_commit() { asm volatile("cp.async.commit_group;"); }
__device__ __forceinline__ void cpa_wait1()  { asm volatile("cp.async.wait_group 1;"); }
__device__ __forceinline__ void cpa_wait0()  { asm volatile("cp.async.wait_group 0;"); }

// ================= fused prep: weights + inputs + pstat =================
__global__ __launch_bounds__(256) void prep_all(
    const float* __restrict__ wq, const float* __restrict__ wk,
    const float* __restrict__ wv, const float* __restrict__ p2w,
    const float* __restrict__ wo, const float* __restrict__ A,
    const float* __restrict__ p1w, const float* __restrict__ p1b,
    const float* __restrict__ lng)
{
    __shared__ float t[64][65];
    __shared__ float red[8];
    const int bid = blockIdx.x;
    const int tid = threadIdx.x;

    if (bid < 80) {
        const int w = bid >> 4;
        const float* src = (w == 0) ? wq : (w == 1) ? wk : (w == 2) ? wv :
                           (w == 3) ? p2w : wo;
        const int y = bid & 15;
        const int n0 = (y & 3) * 64, k0 = (y >> 2) * 64;
#pragma unroll
        for (int i = 0; i < 4; i++) {
            int f = i * 256 + tid;
            int kr = f >> 4, nc = (f & 15) * 4;
            float4 v = *(const float4*)(src + (size_t)(k0 + kr) * 256 + n0 + nc);
            t[kr][nc] = v.x; t[kr][nc+1] = v.y; t[kr][nc+2] = v.z; t[kr][nc+3] = v.w;
        }
        __syncthreads();
#pragma unroll
        for (int i = 0; i < 4; i++) {
            int f = i * 256 + tid;
            int nr = f >> 4, kc = (f & 15) * 4;
            size_t o = (size_t)w * 65536 + (size_t)(n0 + nr) * 256 + k0 + kc;
#pragma unroll
            for (int j = 0; j < 4; j++) {
                float v = t[kc + j][nr] * WSCALE;
                __half h = __float2half_rn(v);
                g_wh[o + j] = h;
                g_wl[o + j] = __float2half_rn(v - __half2float(h));
            }
        }
    } else if (bid < 2128) {
        const int idx = ((bid - 80) * 256 + tid) * 4;
        float4 v = *(const float4*)(A + idx);
        uint2 o;
        o.x = pkhf(v.x, v.y);
        o.y = pkhf(v.z, v.w);
        *(uint2*)(&g_af[idx]) = o;
    } else {
        const int lane = tid & 31, warp = tid >> 5;
        float w0 = p1w[tid], w1 = p1w[256 + tid], b0 = p1b[tid];
        float sums[3] = {w0, w1, b0};
        float means[3];
#pragma unroll
        for (int s = 0; s < 3; s++) {
            float v = sums[s];
#pragma unroll
            for (int o = 16; o; o >>= 1) v += __shfl_xor_sync(0xffffffffu, v, o);
            if (lane == 0) red[warp] = v;
            __syncthreads();
            float tot = 0.f;
#pragma unroll
            for (int i = 0; i < 8; i++) tot += red[i];
            means[s] = tot * (1.f / 256.f);
            __syncthreads();
        }
        float a = w0 - means[0], b = w1 - means[1], c = b0 - means[2];
        float g = lng[tid];
        g_A2[tid] = a * g; g_B2[tid] = b * g; g_C2[tid] = c * g;

        float prods[6] = {a*a, b*b, a*b, a*c, b*c, c*c};
#pragma unroll
        for (int s = 0; s < 6; s++) {
            float v = prods[s];
#pragma unroll
            for (int o = 16; o; o >>= 1) v += __shfl_xor_sync(0xffffffffu, v, o);
            if (lane == 0) red[warp] = v;
            __syncthreads();
            if (tid == 0) {
                float tot = 0.f;
#pragma unroll
                for (int i = 0; i < 8; i++) tot += red[i];
                g_pstat[s] = tot * (1.f / 256.f);
            }
            __syncthreads();
        }
    }
}

// pos1: reduction-free, 8 values/thread, writes fp16
__global__ __launch_bounds__(256) void pos1_k(
    const float* __restrict__ p, const float* __restrict__ lnb)
{
    const int idx = blockIdx.x * 256 + threadIdx.x;
    const int tok = idx >> 5;
    const int n0 = (idx & 31) * 8;
    const float p0 = p[tok * 2 + 0];
    const float p1 = p[tok * 2 + 1];
    const float var = p0*p0*g_pstat[0] + p1*p1*g_pstat[1] + 2.f*p0*p1*g_pstat[2]
                    + 2.f*p0*g_pstat[3] + 2.f*p1*g_pstat[4] + g_pstat[5];
    const float rstd = rsqrtf(var + 1e-6f);

    float y[8];
#pragma unroll
    for (int i = 0; i < 8; i += 4) {
        float4 a4 = *(const float4*)(g_A2 + n0 + i);
        float4 b4 = *(const float4*)(g_B2 + n0 + i);
        float4 c4 = *(const float4*)(g_C2 + n0 + i);
        float4 bb = *(const float4*)(lnb + n0 + i);
        y[i+0] = gelu_exact((p0*a4.x + p1*b4.x + c4.x) * rstd + bb.x);
        y[i+1] = gelu_exact((p0*a4.y + p1*b4.y + c4.y) * rstd + bb.y);
        y[i+2] = gelu_exact((p0*a4.z + p1*b4.z + c4.z) * rstd + bb.z);
        y[i+3] = gelu_exact((p0*a4.w + p1*b4.w + c4.w) * rstd + bb.w);
    }
    uint4 o;
    o.x = pkhf(y[0], y[1]); o.y = pkhf(y[2], y[3]);
    o.z = pkhf(y[4], y[5]); o.w = pkhf(y[6], y[7]);
    *(uint4*)(&g_pe1[(size_t)tok * 256 + n0]) = o;
}

// ================= fp16 2-term GEMM, BM=64/BN=128/BK=64 (2 blocks/SM) =================
#define OA  0
#define OWH 9216
#define OWL 27648
#define STG 46080
#define GSMEM (2*STG)   // 92160

extern __shared__ char dsm[];

__device__ __forceinline__ void tile_loads(
    const __half* Af, const __half* Wh, const __half* Wl,
    int m0, int n0, int kt, int st, uint32_t smem_u32, int tid)
{
    const uint32_t sb = smem_u32 + st * STG;
    // A: 64 rows x 128B = 512 chunks -> 2/thread
#pragma unroll
    for (int i = 0; i < 2; i++) {
        int f = i * 256 + tid;
        int row = f >> 3, ch = f & 7;
        cpa16(sb + OA + row * 144 + ch * 16,
              Af + (size_t)(m0 + row) * 256 + kt * 64 + ch * 8);
    }
    // W hi/lo: 128 rows x 128B = 1024 chunks each -> 4/thread each
#pragma unroll
    for (int i = 0; i < 4; i++) {
        int f = i * 256 + tid;
        int row = f >> 3, ch = f & 7;
        const uint32_t so = row * 144 + ch * 16;
        const size_t gkb = (size_t)(n0 + row) * 256 + kt * 64 + ch * 8;
        cpa16(sb + OWH + so, Wh + gkb);
        cpa16(sb + OWL + so, Wl + gkb);
    }
}

// If Ch != nullptr -> write fp16 to Ch, else fp32 to Cf.
__device__ __forceinline__ void gemm_core(
    const __half* __restrict__ Af,
    const __half* __restrict__ Wh, const __half* __restrict__ Wl,
    const float* __restrict__ bias, float* __restrict__ Cf,
    __half* __restrict__ Ch,
    float scale, int act, int bx, int by)
{
    const int tid  = threadIdx.x;
    const int wid  = tid >> 5;
    const int lane = tid & 31;
    const int g = lane >> 2;
    const int q = lane & 3;
    const int wm = (wid & 1) * 32;     // 2 m-warps over BM=64
    const int wn = (wid >> 1) * 32;    // 4 n-warps over BN=128
    const int m0 = bx * 64;
    const int n0 = by * 128;
    const uint32_t smem_u32 = (uint32_t)__cvta_generic_to_shared(dsm);

    float acc[2][4][4];
#pragma unroll
    for (int mt = 0; mt < 2; mt++)
#pragma unroll
        for (int nt = 0; nt < 4; nt++)
#pragma unroll
            for (int i = 0; i < 4; i++) acc[mt][nt][i] = 0.f;

    tile_loads(Af, Wh, Wl, m0, n0, 0, 0, smem_u32, tid);
    cpa_commit();

    const int la = lane & 15;
    const int khalf = (lane >> 4) * 16;

    for (int it = 0; it < 4; it++) {
        if (it < 3) {
            tile_loads(Af, Wh, Wl, m0, n0, it + 1, (it + 1) & 1, smem_u32, tid);
            cpa_commit();
            cpa_wait1();
        } else {
            cpa_wait0();
        }
        __syncthreads();

        const char* sb = dsm + (it & 1) * STG;
#pragma unroll
        for (int ks = 0; ks < 4; ks++) {
            const int kb = ks * 32 + khalf;
            uint32_t a[2][4], bh[2][4], bl[2][4];
#pragma unroll
            for (int mt = 0; mt < 2; mt++)
                ldsm4(a[mt], sb + OA + (wm + mt * 16 + la) * 144 + kb);
#pragma unroll
            for (int np = 0; np < 2; np++) {
                ldsm4(bh[np], sb + OWH + (wn + np * 16 + la) * 144 + kb);
                ldsm4(bl[np], sb + OWL + (wn + np * 16 + la) * 144 + kb);
            }
#pragma unroll
            for (int mt = 0; mt < 2; mt++)
#pragma unroll
                for (int nt = 0; nt < 4; nt++) {
                    const int np = nt >> 1, j = nt & 1;
                    mma_f16(acc[mt][nt], a[mt], bh[np][j], bh[np][j + 2]);
                    mma_f16(acc[mt][nt], a[mt], bl[np][j], bl[np][j + 2]);
                }
        }
        __syncthreads();
    }

#pragma unroll
    for (int mt = 0; mt < 2; mt++) {
        int r0 = m0 + wm + mt * 16 + g;
#pragma unroll
        for (int nt = 0; nt < 4; nt++) {
            int cn = n0 + wn + nt * 8 + 2 * q;
            float2 b2 = *(const float2*)(bias + cn);
            float v0 = (acc[mt][nt][0] * WSCALE_INV + b2.x) * scale;
            float v1 = (acc[mt][nt][1] * WSCALE_INV + b2.y) * scale;
            float v2 = (acc[mt][nt][2] * WSCALE_INV + b2.x) * scale;
            float v3 = (acc[mt][nt][3] * WSCALE_INV + b2.y) * scale;
            if (act) {
                v0 = gelu_exact(v0); v1 = gelu_exact(v1);
                v2 = gelu_exact(v2); v3 = gelu_exact(v3);
            }
            if (Ch) {
                *(uint32_t*)(Ch + (size_t)r0 * 256 + cn)       = pkhf(v0, v1);
                *(uint32_t*)(Ch + (size_t)(r0 + 8) * 256 + cn) = pkhf(v2, v3);
            } else {
                *(float2*)(Cf + (size_t)r0 * 256 + cn)       = make_float2(v0, v1);
                *(float2*)(Cf + (size_t)(r0 + 8) * 256 + cn) = make_float2(v2, v3);
            }
        }
    }
}

// fused Q/K/V/PE: blockIdx.z selects; all write fp16
__global__ __launch_bounds__(256, 2) void gemm4(
    const float* __restrict__ bq, const float* __restrict__ bk,
    const float* __restrict__ bv, const float* __restrict__ p2b)
{
    const int z = blockIdx.z;
    const __half* Af = (z == 3) ? g_pe1 : g_af;
    const float* bias = (z == 0) ? bq : (z == 1) ? bk : (z == 2) ? bv : p2b;
    __half* Ch = (z == 0) ? g_qf : (z == 1) ? g_kf : (z == 2) ? g_vf : g_pef;
    float scale = (z == 0) ? 0.17677669529663689f : 1.f;
    gemm_core(Af, g_wh + (size_t)z * 65536, g_wl + (size_t)z * 65536,
              bias, nullptr, Ch, scale, (z == 3) ? 1 : 0, blockIdx.x, blockIdx.y);
}
__global__ __launch_bounds__(256, 2) void gemm_out(const float* __restrict__ bo,
                                                   float* __restrict__ out)
{
    gemm_core(g_ctxf, g_wh + (size_t)4 * 65536, g_wl + (size_t)4 * 65536,
              bo, out, nullptr, 1.f, 0, blockIdx.x, blockIdx.y);
}

// ================= windowed attention (R12-proven, fp16 inputs) =================
// S[i,j] = q_i·(k_j - pe_j) + (c·k_j - d·pe_j) + (q_i + d)·pe_i
__global__ __launch_bounds__(128) void attn_k(
    const float* __restrict__ cvec, const float* __restrict__ dvec)
{
    const int w = blockIdx.x, h = blockIdx.y, b = blockIdx.z;

    __shared__ __half sq[64][40];
    __shared__ __half skw[64][40];
    __shared__ __half sv[64][40];
    __shared__ float sbias[64];
    __shared__ float su[64];

    const int t = threadIdx.x;
    const int tok = t >> 1;
    const int l = t & 1;
    const int dl = l * 16;

    const int s = w * 64 + tok;
    const int o = s >> 4, r = s & 15;
    const int ic = ((o & 63) << 1) + (o >> 6);
    const int orig = ic * 16 + r;
    const size_t base = ((size_t)(b * SEQ + orig)) * 256 + h * 32 + dl;

    const float* cp = cvec + h * 32 + dl;
    const float* dp = dvec + h * 32 + dl;

    float bias_p = 0.f, u_p = 0.f;
#pragma unroll
    for (int i = 0; i < 16; i += 8) {
        uint4 xq = *(const uint4*)(g_qf + base + i);
        uint4 xk = *(const uint4*)(g_kf + base + i);
        uint4 xv = *(const uint4*)(g_vf + base + i);
        uint4 xp = *(const uint4*)(g_pef + base + i);
        float4 xc0 = *(const float4*)(cp + i);
        float4 xc1 = *(const float4*)(cp + i + 4);
        float4 xd0 = *(const float4*)(dp + i);
        float4 xd1 = *(const float4*)(dp + i + 4);

        *(uint4*)(&sq[tok][dl + i]) = xq;
        *(uint4*)(&sv[tok][dl + i]) = xv;

        uint4 kw;
        const __half2* k2 = (const __half2*)&xk;
        const __half2* p2 = (const __half2*)&xp;
        const __half2* q2 = (const __half2*)&xq;
        __half2* w2 = (__half2*)&kw;
#pragma unroll
        for (int j = 0; j < 4; j++) w2[j] = __hsub2(k2[j], p2[j]);
        *(uint4*)(&skw[tok][dl + i]) = kw;

        float cv4[8] = {xc0.x, xc0.y, xc0.z, xc0.w, xc1.x, xc1.y, xc1.z, xc1.w};
        float dv4[8] = {xd0.x, xd0.y, xd0.z, xd0.w, xd1.x, xd1.y, xd1.z, xd1.w};
#pragma unroll
        for (int j = 0; j < 4; j++) {
            float2 fk = __half22float2(k2[j]);
            float2 fp = __half22float2(p2[j]);
            float2 fq = __half22float2(q2[j]);
            bias_p += cv4[2*j] * fk.x + cv4[2*j+1] * fk.y;
            bias_p -= dv4[2*j] * fp.x + dv4[2*j+1] * fp.y;
            u_p += (fq.x + dv4[2*j]) * fp.x + (fq.y + dv4[2*j+1]) * fp.y;
        }
    }
    bias_p += __shfl_xor_sync(0xffffffffu, bias_p, 1);
    u_p    += __shfl_xor_sync(0xffffffffu, u_p, 1);
    if (l == 0) { sbias[tok] = bias_p; su[tok] = u_p; }
    __syncthreads();

    const int warp = t >> 5, lane = t & 31;
    const int la = lane & 15, lo8 = (lane >> 4) << 3;
    const int g = lane >> 2, q = lane & 3;
    const int r0 = warp * 16;

    float sacc[8][4];
#pragma unroll
    for (int j = 0; j < 8; j++)
#pragma unroll
        for (int i = 0; i < 4; i++) sacc[j][i] = 0.f;

#pragma unroll
    for (int ks = 0; ks < 2; ks++) {
        uint32_t a[4];
        ldsm4(a, &sq[r0 + la][ks * 16 + lo8]);
#pragma unroll
        for (int np = 0; np < 4; np++) {
            uint32_t bk[4];
            ldsm4(bk, &skw[np * 16 + la][ks * 16 + lo8]);
            mma_f16(sacc[2 * np],     a, bk[0], bk[2]);
            mma_f16(sacc[2 * np + 1], a, bk[1], bk[3]);
        }
    }

    const int rg = r0 + g;
    const float ug  = su[rg];
    const float ug8 = su[rg + 8];
    float m1 = -1e30f, m2 = -1e30f;
#pragma unroll
    for (int j = 0; j < 8; j++) {
        const int c0 = 8 * j + 2 * q;
        const float b0 = sbias[c0], b1 = sbias[c0 + 1];
        sacc[j][0] += ug  + b0; sacc[j][1] += ug  + b1;
        sacc[j][2] += ug8 + b0; sacc[j][3] += ug8 + b1;
        m1 = fmaxf(m1, fmaxf(sacc[j][0], sacc[j][1]));
        m2 = fmaxf(m2, fmaxf(sacc[j][2], sacc[j][3]));
    }
    m1 = fmaxf(m1, __shfl_xor_sync(0xffffffffu, m1, 1));
    m1 = fmaxf(m1, __shfl_xor_sync(0xffffffffu, m1, 2));
    m2 = fmaxf(m2, __shfl_xor_sync(0xffffffffu, m2, 1));
    m2 = fmaxf(m2, __shfl_xor_sync(0xffffffffu, m2, 2));

    float s1 = 0.f, s2 = 0.f;
    uint32_t pf[8], ph[8];
#pragma unroll
    for (int j = 0; j < 8; j++) {
        float e0 = __expf(sacc[j][0] - m1);
        float e1 = __expf(sacc[j][1] - m1);
        float e2 = __expf(sacc[j][2] - m2);
        float e3 = __expf(sacc[j][3] - m2);
        s1 += e0 + e1; s2 += e2 + e3;
        pf[j] = pkhf(e0, e1);
        ph[j] = pkhf(e2, e3);
    }
    s1 += __shfl_xor_sync(0xffffffffu, s1, 1);
    s1 += __shfl_xor_sync(0xffffffffu, s1, 2);
    s2 += __shfl_xor_sync(0xffffffffu, s2, 1);
    s2 += __shfl_xor_sync(0xffffffffu, s2, 2);
    const float inv1 = 1.f / s1;
    const float inv2 = 1.f / s2;

    float oacc[4][4];
#pragma unroll
    for (int j = 0; j < 4; j++)
#pragma unroll
        for (int i = 0; i < 4; i++) oacc[j][i] = 0.f;

#pragma unroll
    for (int kk = 0; kk < 4; kk++) {
        uint32_t a[4] = {pf[2 * kk], ph[2 * kk], pf[2 * kk + 1], ph[2 * kk + 1]};
#pragma unroll
        for (int np = 0; np < 2; np++) {
            uint32_t bv[4];
            ldsm4t(bv, &sv[kk * 16 + la][np * 16 + lo8]);
            mma_f16(oacc[2 * np],     a, bv[0], bv[1]);
            mma_f16(oacc[2 * np + 1], a, bv[2], bv[3]);
        }
    }

    {
        const int s_a = w * 64 + rg;
        const int oa_ = s_a >> 4, ra_ = s_a & 15;
        const int orig_a = (((oa_ & 63) << 1) + (oa_ >> 6)) * 16 + ra_;
        const size_t ba = ((size_t)(b * SEQ + orig_a)) * 256 + h * 32;
        const int s_b2 = w * 64 + rg + 8;
        const int ob_ = s_b2 >> 4, rb_ = s_b2 & 15;
        const int orig_b = (((ob_ & 63) << 1) + (ob_ >> 6)) * 16 + rb_;
        const size_t bb = ((size_t)(b * SEQ + orig_b)) * 256 + h * 32;
#pragma unroll
        for (int nt = 0; nt < 4; nt++) {
            const int d0 = 8 * nt + 2 * q;
            *(uint32_t*)(&g_ctxf[ba + d0]) = pkhf(oacc[nt][0] * inv1, oacc[nt][1] * inv1);
            *(uint32_t*)(&g_ctxf[bb + d0]) = pkhf(oacc[nt][2] * inv2, oacc[nt][3] * inv2);
        }
    }
}

// ================= launch =================
extern "C" void kernel_launch(void* const* d_in, const int* in_sizes, int n_in,
                              void* d_out, int out_size)
{
    const float* inputs = (const float*)d_in[0];
    const float* p      = (const float*)d_in[1];
    const float* wq     = (const float*)d_in[2];
    const float* bq     = (const float*)d_in[3];
    const float* wk     = (const float*)d_in[4];
    const float* bk     = (const float*)d_in[5];
    const float* wv     = (const float*)d_in[6];
    const float* bv     = (const float*)d_in[7];
    const float* wo     = (const float*)d_in[8];
    const float* bo     = (const float*)d_in[9];
    const float* p1w    = (const float*)d_in[10];
    const float* p1b    = (const float*)d_in[11];
    const float* p2w    = (const float*)d_in[12];
    const float* p2b    = (const float*)d_in[13];
    const float* lng    = (const float*)d_in[14];
    const float* lnb    = (const float*)d_in[15];
    const float* cv     = (const float*)d_in[16];
    const float* dv     = (const float*)d_in[17];
    float* out = (float*)d_out;

    cudaFuncSetAttribute(gemm4,    cudaFuncAttributeMaxDynamicSharedMemorySize, GSMEM);
    cudaFuncSetAttribute(gemm_out, cudaFuncAttributeMaxDynamicSharedMemorySize, GSMEM);

    prep_all<<<2129, 256>>>(wq, wk, wv, p2w, wo, inputs, p1w, p1b, lng);
    pos1_k<<<NTOK * 32 / 256, 256>>>(p, lnb);
    gemm4<<<dim3(128, 2, 4), 256, GSMEM>>>(bq, bk, bv, p2b);
    attn_k<<<dim3(NWIN, NHEAD, BATCH), 128>>>(cv, dv);
    gemm_out<<<dim3(128, 2), 256, GSMEM>>>(bo, out);
}

// round 15
// speedup vs baseline: 1.1691x; 1.0135x over previous
#include <cuda_runtime.h>
#include <cuda_fp16.h>
#include <math.h>
#include <stdint.h>

#define BATCH 4
#define SEQ   2048
#define HID   256
#define NTOK  (BATCH*SEQ)   // 8192
#define NHEAD 8
#define DPH   32
#define WINSZ 64
#define NWIN  32

#define WSCALE     256.0f
#define WSCALE_INV 0.00390625f

// ---------------- scratch (no allocs allowed) ----------------
__device__ __half g_qf[NTOK*HID];     // q (scaled) fp16
__device__ __half g_kf[NTOK*HID];     // k fp16
__device__ __half g_vf[NTOK*HID];     // v fp16
__device__ __half g_pef[NTOK*HID];    // pe fp16

__device__ __half g_af[NTOK*HID];     // inputs fp16
__device__ __half g_pe1[NTOK*HID];    // pos-mlp stage1 fp16
__device__ __half g_ctxf[NTOK*HID];   // attn output fp16
__device__ __half g_wh[5*HID*HID];    // weights*256, TRANSPOSED [n][k], fp16 hi
__device__ __half g_wl[5*HID*HID];    // residual lo

__device__ float g_A2[HID], g_B2[HID], g_C2[HID];  // centered pos1 weights * ln_g
__device__ float g_pstat[6];                       // Saa,Sbb,Sab,Sac,Sbc,Scc

__device__ __forceinline__ float gelu_exact(float x) {
    return 0.5f * x * (1.0f + erff(x * 0.70710678118654752f));
}
__device__ __forceinline__ uint32_t pkhf(float a, float b) {
    __half2 h = __floats2half2_rn(a, b);
    return *reinterpret_cast<uint32_t*>(&h);
}

__device__ __forceinline__ void ldsm4(uint32_t* r, const void* p) {
    uint32_t a = (uint32_t)__cvta_generic_to_shared(p);
    asm volatile("ldmatrix.sync.aligned.m8n8.x4.shared.b16 {%0,%1,%2,%3}, [%4];"
                 : "=r"(r[0]), "=r"(r[1]), "=r"(r[2]), "=r"(r[3]) : "r"(a));
}
__device__ __forceinline__ void ldsm4t(uint32_t* r, const void* p) {
    uint32_t a = (uint32_t)__cvta_generic_to_shared(p);
    asm volatile("ldmatrix.sync.aligned.m8n8.x4.trans.shared.b16 {%0,%1,%2,%3}, [%4];"
                 : "=r"(r[0]), "=r"(r[1]), "=r"(r[2]), "=r"(r[3]) : "r"(a));
}
__device__ __forceinline__ void mma_f16(float* d, const uint32_t* a,
                                        uint32_t b0, uint32_t b1) {
    asm volatile(
        "mma.sync.aligned.m16n8k16.row.col.f32.f16.f16.f32 "
        "{%0,%1,%2,%3}, {%4,%5,%6,%7}, {%8,%9}, {%0,%1,%2,%3};\n"
        : "+f"(d[0]), "+f"(d[1]), "+f"(d[2]), "+f"(d[3])
        : "r"(a[0]), "r"(a[1]), "r"(a[2]), "r"(a[3]), "r"(b0), "r"(b1));
}
__device__ __forceinline__ void cpa16(uint32_t s, const void* g) {
    asm volatile("cp.async.cg.shared.global [%0], [%1], 16;" :: "r"(s), "l"(g));
}
__device__ __forceinline__ void cpa_commit() { asm volatile("cp.async.commit_group;"); }
__device__ __forceinline__ void cpa_wait1()  { asm volatile("cp.async.wait_group 1;"); }
__device__ __forceinline__ void cpa_wait0()  { asm volatile("cp.async.wait_group 0;"); }

// ================= fused prep: weights + inputs + pstat =================
__global__ __launch_bounds__(256) void prep_all(
    const float* __restrict__ wq, const float* __restrict__ wk,
    const float* __restrict__ wv, const float* __restrict__ p2w,
    const float* __restrict__ wo, const float* __restrict__ A,
    const float* __restrict__ p1w, const float* __restrict__ p1b,
    const float* __restrict__ lng)
{
    __shared__ float t[64][65];
    __shared__ float red[8];
    const int bid = blockIdx.x;
    const int tid = threadIdx.x;

    if (bid < 80) {
        const int w = bid >> 4;
        const float* src = (w == 0) ? wq : (w == 1) ? wk : (w == 2) ? wv :
                           (w == 3) ? p2w : wo;
        const int y = bid & 15;
        const int n0 = (y & 3) * 64, k0 = (y >> 2) * 64;
#pragma unroll
        for (int i = 0; i < 4; i++) {
            int f = i * 256 + tid;
            int kr = f >> 4, nc = (f & 15) * 4;
            float4 v = *(const float4*)(src + (size_t)(k0 + kr) * 256 + n0 + nc);
            t[kr][nc] = v.x; t[kr][nc+1] = v.y; t[kr][nc+2] = v.z; t[kr][nc+3] = v.w;
        }
        __syncthreads();
#pragma unroll
        for (int i = 0; i < 4; i++) {
            int f = i * 256 + tid;
            int nr = f >> 4, kc = (f & 15) * 4;
            size_t o = (size_t)w * 65536 + (size_t)(n0 + nr) * 256 + k0 + kc;
#pragma unroll
            for (int j = 0; j < 4; j++) {
                float v = t[kc + j][nr] * WSCALE;
                __half h = __float2half_rn(v);
                g_wh[o + j] = h;
                g_wl[o + j] = __float2half_rn(v - __half2float(h));
            }
        }
    } else if (bid < 2128) {
        const int idx = ((bid - 80) * 256 + tid) * 4;
        float4 v = *(const float4*)(A + idx);
        uint2 o;
        o.x = pkhf(v.x, v.y);
        o.y = pkhf(v.z, v.w);
        *(uint2*)(&g_af[idx]) = o;
    } else {
        const int lane = tid & 31, warp = tid >> 5;
        float w0 = p1w[tid], w1 = p1w[256 + tid], b0 = p1b[tid];
        float sums[3] = {w0, w1, b0};
        float means[3];
#pragma unroll
        for (int s = 0; s < 3; s++) {
            float v = sums[s];
#pragma unroll
            for (int o = 16; o; o >>= 1) v += __shfl_xor_sync(0xffffffffu, v, o);
            if (lane == 0) red[warp] = v;
            __syncthreads();
            float tot = 0.f;
#pragma unroll
            for (int i = 0; i < 8; i++) tot += red[i];
            means[s] = tot * (1.f / 256.f);
            __syncthreads();
        }
        float a = w0 - means[0], b = w1 - means[1], c = b0 - means[2];
        float g = lng[tid];
        g_A2[tid] = a * g; g_B2[tid] = b * g; g_C2[tid] = c * g;

        float prods[6] = {a*a, b*b, a*b, a*c, b*c, c*c};
#pragma unroll
        for (int s = 0; s < 6; s++) {
            float v = prods[s];
#pragma unroll
            for (int o = 16; o; o >>= 1) v += __shfl_xor_sync(0xffffffffu, v, o);
            if (lane == 0) red[warp] = v;
            __syncthreads();
            if (tid == 0) {
                float tot = 0.f;
#pragma unroll
                for (int i = 0; i < 8; i++) tot += red[i];
                g_pstat[s] = tot * (1.f / 256.f);
            }
            __syncthreads();
        }
    }
}

// pos1: reduction-free, 8 values/thread, writes fp16
__global__ __launch_bounds__(256) void pos1_k(
    const float* __restrict__ p, const float* __restrict__ lnb)
{
    const int idx = blockIdx.x * 256 + threadIdx.x;
    const int tok = idx >> 5;
    const int n0 = (idx & 31) * 8;
    const float p0 = p[tok * 2 + 0];
    const float p1 = p[tok * 2 + 1];
    const float var = p0*p0*g_pstat[0] + p1*p1*g_pstat[1] + 2.f*p0*p1*g_pstat[2]
                    + 2.f*p0*g_pstat[3] + 2.f*p1*g_pstat[4] + g_pstat[5];
    const float rstd = rsqrtf(var + 1e-6f);

    float y[8];
#pragma unroll
    for (int i = 0; i < 8; i += 4) {
        float4 a4 = *(const float4*)(g_A2 + n0 + i);
        float4 b4 = *(const float4*)(g_B2 + n0 + i);
        float4 c4 = *(const float4*)(g_C2 + n0 + i);
        float4 bb = *(const float4*)(lnb + n0 + i);
        y[i+0] = gelu_exact((p0*a4.x + p1*b4.x + c4.x) * rstd + bb.x);
        y[i+1] = gelu_exact((p0*a4.y + p1*b4.y + c4.y) * rstd + bb.y);
        y[i+2] = gelu_exact((p0*a4.z + p1*b4.z + c4.z) * rstd + bb.z);
        y[i+3] = gelu_exact((p0*a4.w + p1*b4.w + c4.w) * rstd + bb.w);
    }
    uint4 o;
    o.x = pkhf(y[0], y[1]); o.y = pkhf(y[2], y[3]);
    o.z = pkhf(y[4], y[5]); o.w = pkhf(y[6], y[7]);
    *(uint4*)(&g_pe1[(size_t)tok * 256 + n0]) = o;
}

// ================= fp16 2-term GEMM, BM=64/BN=128/BK=64 (2 blocks/SM) =================
#define OA  0
#define OWH 9216
#define OWL 27648
#define STG 46080
#define GSMEM (2*STG)   // 92160

extern __shared__ char dsm[];

__device__ __forceinline__ void tile_loads(
    const __half* Af, const __half* Wh, const __half* Wl,
    int m0, int n0, int kt, int st, uint32_t smem_u32, int tid)
{
    const uint32_t sb = smem_u32 + st * STG;
#pragma unroll
    for (int i = 0; i < 2; i++) {
        int f = i * 256 + tid;
        int row = f >> 3, ch = f & 7;
        cpa16(sb + OA + row * 144 + ch * 16,
              Af + (size_t)(m0 + row) * 256 + kt * 64 + ch * 8);
    }
#pragma unroll
    for (int i = 0; i < 4; i++) {
        int f = i * 256 + tid;
        int row = f >> 3, ch = f & 7;
        const uint32_t so = row * 144 + ch * 16;
        const size_t gkb = (size_t)(n0 + row) * 256 + kt * 64 + ch * 8;
        cpa16(sb + OWH + so, Wh + gkb);
        cpa16(sb + OWL + so, Wl + gkb);
    }
}

// If Ch != nullptr -> write fp16 to Ch, else fp32 to Cf.
__device__ __forceinline__ void gemm_core(
    const __half* __restrict__ Af,
    const __half* __restrict__ Wh, const __half* __restrict__ Wl,
    const float* __restrict__ bias, float* __restrict__ Cf,
    __half* __restrict__ Ch,
    float scale, int act, int bx, int by)
{
    const int tid  = threadIdx.x;
    const int wid  = tid >> 5;
    const int lane = tid & 31;
    const int g = lane >> 2;
    const int q = lane & 3;
    const int wm = (wid & 1) * 32;
    const int wn = (wid >> 1) * 32;
    const int m0 = bx * 64;
    const int n0 = by * 128;
    const uint32_t smem_u32 = (uint32_t)__cvta_generic_to_shared(dsm);

    float acc[2][4][4];
#pragma unroll
    for (int mt = 0; mt < 2; mt++)
#pragma unroll
        for (int nt = 0; nt < 4; nt++)
#pragma unroll
            for (int i = 0; i < 4; i++) acc[mt][nt][i] = 0.f;

    tile_loads(Af, Wh, Wl, m0, n0, 0, 0, smem_u32, tid);
    cpa_commit();

    const int la = lane & 15;
    const int khalf = (lane >> 4) * 16;

    for (int it = 0; it < 4; it++) {
        if (it < 3) {
            tile_loads(Af, Wh, Wl, m0, n0, it + 1, (it + 1) & 1, smem_u32, tid);
            cpa_commit();
            cpa_wait1();
        } else {
            cpa_wait0();
        }
        __syncthreads();

        const char* sb = dsm + (it & 1) * STG;
#pragma unroll
        for (int ks = 0; ks < 4; ks++) {
            const int kb = ks * 32 + khalf;
            uint32_t a[2][4], bh[2][4], bl[2][4];
#pragma unroll
            for (int mt = 0; mt < 2; mt++)
                ldsm4(a[mt], sb + OA + (wm + mt * 16 + la) * 144 + kb);
#pragma unroll
            for (int np = 0; np < 2; np++) {
                ldsm4(bh[np], sb + OWH + (wn + np * 16 + la) * 144 + kb);
                ldsm4(bl[np], sb + OWL + (wn + np * 16 + la) * 144 + kb);
            }
#pragma unroll
            for (int mt = 0; mt < 2; mt++)
#pragma unroll
                for (int nt = 0; nt < 4; nt++) {
                    const int np = nt >> 1, j = nt & 1;
                    mma_f16(acc[mt][nt], a[mt], bh[np][j], bh[np][j + 2]);
                    mma_f16(acc[mt][nt], a[mt], bl[np][j], bl[np][j + 2]);
                }
        }
        __syncthreads();
    }

#pragma unroll
    for (int mt = 0; mt < 2; mt++) {
        int r0 = m0 + wm + mt * 16 + g;
#pragma unroll
        for (int nt = 0; nt < 4; nt++) {
            int cn = n0 + wn + nt * 8 + 2 * q;
            float2 b2 = *(const float2*)(bias + cn);
            float v0 = (acc[mt][nt][0] * WSCALE_INV + b2.x) * scale;
            float v1 = (acc[mt][nt][1] * WSCALE_INV + b2.y) * scale;
            float v2 = (acc[mt][nt][2] * WSCALE_INV + b2.x) * scale;
            float v3 = (acc[mt][nt][3] * WSCALE_INV + b2.y) * scale;
            if (act) {
                v0 = gelu_exact(v0); v1 = gelu_exact(v1);
                v2 = gelu_exact(v2); v3 = gelu_exact(v3);
            }
            if (Ch) {
                *(uint32_t*)(Ch + (size_t)r0 * 256 + cn)       = pkhf(v0, v1);
                *(uint32_t*)(Ch + (size_t)(r0 + 8) * 256 + cn) = pkhf(v2, v3);
            } else {
                *(float2*)(Cf + (size_t)r0 * 256 + cn)       = make_float2(v0, v1);
                *(float2*)(Cf + (size_t)(r0 + 8) * 256 + cn) = make_float2(v2, v3);
            }
        }
    }
}

// fused Q/K/V/PE: blockIdx.z selects; all write fp16
__global__ __launch_bounds__(256, 2) void gemm4(
    const float* __restrict__ bq, const float* __restrict__ bk,
    const float* __restrict__ bv, const float* __restrict__ p2b)
{
    const int z = blockIdx.z;
    const __half* Af = (z == 3) ? g_pe1 : g_af;
    const float* bias = (z == 0) ? bq : (z == 1) ? bk : (z == 2) ? bv : p2b;
    __half* Ch = (z == 0) ? g_qf : (z == 1) ? g_kf : (z == 2) ? g_vf : g_pef;
    float scale = (z == 0) ? 0.17677669529663689f : 1.f;
    gemm_core(Af, g_wh + (size_t)z * 65536, g_wl + (size_t)z * 65536,
              bias, nullptr, Ch, scale, (z == 3) ? 1 : 0, blockIdx.x, blockIdx.y);
}
__global__ __launch_bounds__(256, 2) void gemm_out(const float* __restrict__ bo,
                                                   float* __restrict__ out)
{
    gemm_core(g_ctxf, g_wh + (size_t)4 * 65536, g_wl + (size_t)4 * 65536,
              bo, out, nullptr, 1.f, 0, blockIdx.x, blockIdx.y);
}

// ================= windowed attention: 4 threads/token gather+scatter =================
// S[i,j] = q_i·(k_j - pe_j) + (c·k_j - d·pe_j) + (q_i + d)·pe_i
__global__ __launch_bounds__(128) void attn_k(
    const float* __restrict__ cvec, const float* __restrict__ dvec)
{
    const int w = blockIdx.x, h = blockIdx.y, b = blockIdx.z;

    __shared__ __half sq[64][40];
    __shared__ __half skw[64][40];   // reused for output staging after S-MMA
    __shared__ __half sv[64][40];
    __shared__ float sbias[64];
    __shared__ float su[64];

    const int t = threadIdx.x;
    const int l = t & 3;
    const int dl = l * 8;

    // ---- gather: 4 threads per token (full 64B row per warp-quad) ----
#pragma unroll
    for (int tt = 0; tt < 2; tt++) {
        const int tok = (t >> 2) + 32 * tt;
        const int s = w * 64 + tok;
        const int o = s >> 4, r = s & 15;
        const int orig = (((o & 63) << 1) + (o >> 6)) * 16 + r;
        const size_t base = ((size_t)(b * SEQ + orig)) * 256 + h * 32 + dl;

        uint4 xq = *(const uint4*)(g_qf + base);
        uint4 xk = *(const uint4*)(g_kf + base);
        uint4 xv = *(const uint4*)(g_vf + base);
        uint4 xp = *(const uint4*)(g_pef + base);
        float4 xc0 = *(const float4*)(cvec + h * 32 + dl);
        float4 xc1 = *(const float4*)(cvec + h * 32 + dl + 4);
        float4 xd0 = *(const float4*)(dvec + h * 32 + dl);
        float4 xd1 = *(const float4*)(dvec + h * 32 + dl + 4);

        *(uint4*)(&sq[tok][dl]) = xq;
        *(uint4*)(&sv[tok][dl]) = xv;

        uint4 kw;
        const __half2* k2 = (const __half2*)&xk;
        const __half2* p2 = (const __half2*)&xp;
        const __half2* q2 = (const __half2*)&xq;
        __half2* w2 = (__half2*)&kw;
#pragma unroll
        for (int j = 0; j < 4; j++) w2[j] = __hsub2(k2[j], p2[j]);
        *(uint4*)(&skw[tok][dl]) = kw;

        float cv8[8] = {xc0.x, xc0.y, xc0.z, xc0.w, xc1.x, xc1.y, xc1.z, xc1.w};
        float dv8[8] = {xd0.x, xd0.y, xd0.z, xd0.w, xd1.x, xd1.y, xd1.z, xd1.w};
        float bias_p = 0.f, u_p = 0.f;
#pragma unroll
        for (int j = 0; j < 4; j++) {
            float2 fk = __half22float2(k2[j]);
            float2 fp = __half22float2(p2[j]);
            float2 fq = __half22float2(q2[j]);
            bias_p += cv8[2*j] * fk.x + cv8[2*j+1] * fk.y;
            bias_p -= dv8[2*j] * fp.x + dv8[2*j+1] * fp.y;
            u_p += (fq.x + dv8[2*j]) * fp.x + (fq.y + dv8[2*j+1]) * fp.y;
        }
        bias_p += __shfl_xor_sync(0xffffffffu, bias_p, 1);
        bias_p += __shfl_xor_sync(0xffffffffu, bias_p, 2);
        u_p += __shfl_xor_sync(0xffffffffu, u_p, 1);
        u_p += __shfl_xor_sync(0xffffffffu, u_p, 2);
        if (l == 0) { sbias[tok] = bias_p; su[tok] = u_p; }
    }
    __syncthreads();

    const int warp = t >> 5, lane = t & 31;
    const int la = lane & 15, lo8 = (lane >> 4) << 3;
    const int g = lane >> 2, q = lane & 3;
    const int r0 = warp * 16;

    // ---- S = q @ kw^T (16x64 per warp) ----
    float sacc[8][4];
#pragma unroll
    for (int j = 0; j < 8; j++)
#pragma unroll
        for (int i = 0; i < 4; i++) sacc[j][i] = 0.f;

#pragma unroll
    for (int ks = 0; ks < 2; ks++) {
        uint32_t a[4];
        ldsm4(a, &sq[r0 + la][ks * 16 + lo8]);
#pragma unroll
        for (int np = 0; np < 4; np++) {
            uint32_t bk[4];
            ldsm4(bk, &skw[np * 16 + la][ks * 16 + lo8]);
            mma_f16(sacc[2 * np],     a, bk[0], bk[2]);
            mma_f16(sacc[2 * np + 1], a, bk[1], bk[3]);
        }
    }

    // ---- bias + softmax (rows rg, rg+8) ----
    const int rg = r0 + g;
    const float ug  = su[rg];
    const float ug8 = su[rg + 8];
    float m1 = -1e30f, m2 = -1e30f;
#pragma unroll
    for (int j = 0; j < 8; j++) {
        const int c0 = 8 * j + 2 * q;
        const float b0 = sbias[c0], b1 = sbias[c0 + 1];
        sacc[j][0] += ug  + b0; sacc[j][1] += ug  + b1;
        sacc[j][2] += ug8 + b0; sacc[j][3] += ug8 + b1;
        m1 = fmaxf(m1, fmaxf(sacc[j][0], sacc[j][1]));
        m2 = fmaxf(m2, fmaxf(sacc[j][2], sacc[j][3]));
    }
    m1 = fmaxf(m1, __shfl_xor_sync(0xffffffffu, m1, 1));
    m1 = fmaxf(m1, __shfl_xor_sync(0xffffffffu, m1, 2));
    m2 = fmaxf(m2, __shfl_xor_sync(0xffffffffu, m2, 1));
    m2 = fmaxf(m2, __shfl_xor_sync(0xffffffffu, m2, 2));

    float s1 = 0.f, s2 = 0.f;
    uint32_t pf[8], ph[8];
#pragma unroll
    for (int j = 0; j < 8; j++) {
        float e0 = __expf(sacc[j][0] - m1);
        float e1 = __expf(sacc[j][1] - m1);
        float e2 = __expf(sacc[j][2] - m2);
        float e3 = __expf(sacc[j][3] - m2);
        s1 += e0 + e1; s2 += e2 + e3;
        pf[j] = pkhf(e0, e1);
        ph[j] = pkhf(e2, e3);
    }
    s1 += __shfl_xor_sync(0xffffffffu, s1, 1);
    s1 += __shfl_xor_sync(0xffffffffu, s1, 2);
    s2 += __shfl_xor_sync(0xffffffffu, s2, 1);
    s2 += __shfl_xor_sync(0xffffffffu, s2, 2);
    const float inv1 = 1.f / s1;
    const float inv2 = 1.f / s2;

    // ---- O = P @ V ----
    float oacc[4][4];
#pragma unroll
    for (int j = 0; j < 4; j++)
#pragma unroll
        for (int i = 0; i < 4; i++) oacc[j][i] = 0.f;

#pragma unroll
    for (int kk = 0; kk < 4; kk++) {
        uint32_t a[4] = {pf[2 * kk], ph[2 * kk], pf[2 * kk + 1], ph[2 * kk + 1]};
#pragma unroll
        for (int np = 0; np < 2; np++) {
            uint32_t bv[4];
            ldsm4t(bv, &sv[kk * 16 + la][np * 16 + lo8]);
            mma_f16(oacc[2 * np],     a, bv[0], bv[1]);
            mma_f16(oacc[2 * np + 1], a, bv[2], bv[3]);
        }
    }

    // ---- stage output in smem (reuse skw; all skw reads finished pre-softmax) ----
    __syncthreads();
#pragma unroll
    for (int nt = 0; nt < 4; nt++) {
        const int c0 = 8 * nt + 2 * q;
        *(uint32_t*)(&skw[rg][c0])     = pkhf(oacc[nt][0] * inv1, oacc[nt][1] * inv1);
        *(uint32_t*)(&skw[rg + 8][c0]) = pkhf(oacc[nt][2] * inv2, oacc[nt][3] * inv2);
    }
    __syncthreads();

    // ---- coalesced scatter: 4 threads/token, 16B each ----
#pragma unroll
    for (int tt = 0; tt < 2; tt++) {
        const int tok = (t >> 2) + 32 * tt;
        const int s = w * 64 + tok;
        const int o = s >> 4, r = s & 15;
        const int orig = (((o & 63) << 1) + (o >> 6)) * 16 + r;
        const size_t base = ((size_t)(b * SEQ + orig)) * 256 + h * 32 + dl;
        *(uint4*)(&g_ctxf[base]) = *(const uint4*)(&skw[tok][dl]);
    }
}

// ================= launch =================
extern "C" void kernel_launch(void* const* d_in, const int* in_sizes, int n_in,
                              void* d_out, int out_size)
{
    const float* inputs = (const float*)d_in[0];
    const float* p      = (const float*)d_in[1];
    const float* wq     = (const float*)d_in[2];
    const float* bq     = (const float*)d_in[3];
    const float* wk     = (const float*)d_in[4];
    const float* bk     = (const float*)d_in[5];
    const float* wv     = (const float*)d_in[6];
    const float* bv     = (const float*)d_in[7];
    const float* wo     = (const float*)d_in[8];
    const float* bo     = (const float*)d_in[9];
    const float* p1w    = (const float*)d_in[10];
    const float* p1b    = (const float*)d_in[11];
    const float* p2w    = (const float*)d_in[12];
    const float* p2b    = (const float*)d_in[13];
    const float* lng    = (const float*)d_in[14];
    const float* lnb    = (const float*)d_in[15];
    const float* cv     = (const float*)d_in[16];
    const float* dv     = (const float*)d_in[17];
    float* out = (float*)d_out;

    cudaFuncSetAttribute(gemm4,    cudaFuncAttributeMaxDynamicSharedMemorySize, GSMEM);
    cudaFuncSetAttribute(gemm_out, cudaFuncAttributeMaxDynamicSharedMemorySize, GSMEM);

    prep_all<<<2129, 256>>>(wq, wk, wv, p2w, wo, inputs, p1w, p1b, lng);
    pos1_k<<<NTOK * 32 / 256, 256>>>(p, lnb);
    gemm4<<<dim3(128, 2, 4), 256, GSMEM>>>(bq, bk, bv, p2b);
    attn_k<<<dim3(NWIN, NHEAD, BATCH), 128>>>(cv, dv);
    gemm_out<<<dim3(128, 2), 256, GSMEM>>>(bo, out);
}